// round 16
// baseline (speedup 1.0000x reference)
#include <cuda_runtime.h>
#include <cuda_fp16.h>
#include <cstdint>

// Problem constants (Gemma4 attention): B=2, S=2048, D=2048, H=16, KV=4, HD=256
#define Bc 2
#define Sc 2048
#define Dc 2048
#define Hc 16
#define KVc 4
#define HDc 256
#define NQKV 6144   // H*HD + 2*KV*HD

// Scratch (__device__ globals; no cudaMalloc allowed)
__device__ __half g_qkvh[(size_t)Bc * Sc * NQKV];        // fused QKV out fp16
__device__ __half g_qh[(size_t)Bc * Hc * Sc * HDc];      // [b][h][s][d] (scaled 1/16*log2e)
__device__ __half g_kh[(size_t)Bc * KVc * Sc * HDc];     // [b][kv][s][d]
__device__ __half g_vt[(size_t)Bc * KVc * HDc * Sc];     // [b][kv][d][s]
__device__ __half g_attn_h[(size_t)Bc * Sc * Hc * HDc];  // [b,s][h*HD] fp16
__device__ __half g_hh[(size_t)Bc * Sc * Dc];            // hidden fp16
__device__ __half g_wqkvT[(size_t)NQKV * Dc];            // [6144][2048] fp16
__device__ __half g_woT[(size_t)Dc * (Hc * HDc)];        // [2048][4096]

// ===========================================================================
// Common PTX helpers
// ===========================================================================
__device__ __forceinline__ void cpasync16(const void* smem_dst, const void* gsrc) {
    uint32_t d = (uint32_t)__cvta_generic_to_shared(smem_dst);
    asm volatile("cp.async.cg.shared.global [%0], [%1], 16;" :: "r"(d), "l"(gsrc));
}
#define CP_COMMIT() asm volatile("cp.async.commit_group;" ::: "memory")
#define CP_WAIT0()  asm volatile("cp.async.wait_group 0;" ::: "memory")
#define CP_WAIT1()  asm volatile("cp.async.wait_group 1;" ::: "memory")

#define MMA_F16(d, a, b) \
    asm volatile("mma.sync.aligned.m16n8k16.row.col.f32.f16.f16.f32 " \
                 "{%0,%1,%2,%3}, {%4,%5,%6,%7}, {%8,%9}, {%0,%1,%2,%3};" \
                 : "+f"(d[0]), "+f"(d[1]), "+f"(d[2]), "+f"(d[3]) \
                 : "r"(a[0]), "r"(a[1]), "r"(a[2]), "r"(a[3]), \
                   "r"(b[0]), "r"(b[1]))

__device__ __forceinline__ void ldsm_x4(uint32_t* r, uint32_t saddr) {
    asm volatile("ldmatrix.sync.aligned.m8n8.x4.shared.b16 {%0,%1,%2,%3}, [%4];"
                 : "=r"(r[0]), "=r"(r[1]), "=r"(r[2]), "=r"(r[3]) : "r"(saddr));
}
__device__ __forceinline__ uint32_t packh2(float a, float b) {
    __half2 h = __floats2half2_rn(a, b);
    return *(uint32_t*)&h;
}
__device__ __forceinline__ float ex2(float x) {
    float r;
    asm("ex2.approx.ftz.f32 %0, %1;" : "=f"(r) : "f"(x));
    return r;
}

// ===========================================================================
// fp16 mma.sync GEMM, ldmatrix fragments, 3-stage cp.async pipeline.
// CTA 128x128, 8 warps (2x4), warp tile 64x32, 2 CTAs/SM. Templated output.
// ===========================================================================
#define BM 128
#define BN 128
#define BKH 64
#define PITCH 72
#define NSTG 3
#define STAGE_HALF (2 * 128 * PITCH)
#define STAGE_BYTES (STAGE_HALF * 2)
#define GEMM_SMEM (NSTG * STAGE_BYTES)    // 110592

template <typename OT>
__global__ __launch_bounds__(256, 2) void gemm_f16(
    const __half* __restrict__ A, const __half* __restrict__ Bt,
    OT* __restrict__ C, int M, int N, int K)
{
    extern __shared__ __half smh[];
    const int tid = threadIdx.x;
    const int warp = tid >> 5, lane = tid & 31;
    const int wm = (warp >> 2) * 64, wn = (warp & 3) * 32;
    const int m0 = blockIdx.y * BM, n0 = blockIdx.x * BN;
    const int NT = K / BKH;

    const int sel = lane >> 3, rr = lane & 7;
    const uint32_t sm0 = (uint32_t)__cvta_generic_to_shared(smh);
    const uint32_t aOff = ((uint32_t)(wm + (sel & 1) * 8 + rr) * PITCH + (sel >> 1) * 8) * 2;
    const uint32_t bOff = (uint32_t)(128 * PITCH) * 2 +
                          ((uint32_t)(wn + (sel >> 1) * 8 + rr) * PITCH + (sel & 1) * 8) * 2;

    float acc[4][4][4];
#pragma unroll
    for (int i = 0; i < 4; i++)
#pragma unroll
        for (int j = 0; j < 4; j++)
#pragma unroll
            for (int x = 0; x < 4; x++) acc[i][j][x] = 0.f;

    auto issue = [&](int kt) {
        __half* st = smh + (kt % NSTG) * STAGE_HALF;
        __half* As = st;
        __half* Bs = st + 128 * PITCH;
        const __half* Ag = A + (size_t)m0 * K + kt * BKH;
        const __half* Bg = Bt + (size_t)n0 * K + kt * BKH;
#pragma unroll
        for (int i = 0; i < 4; i++) {
            int idx = tid + i * 256;
            int r = idx >> 3, ch = idx & 7;
            cpasync16(As + r * PITCH + ch * 8, Ag + (size_t)r * K + ch * 8);
        }
#pragma unroll
        for (int i = 0; i < 4; i++) {
            int idx = tid + i * 256;
            int r = idx >> 3, ch = idx & 7;
            cpasync16(Bs + r * PITCH + ch * 8, Bg + (size_t)r * K + ch * 8);
        }
    };

    issue(0); CP_COMMIT();
    issue(1); CP_COMMIT();

    for (int kt = 0; kt < NT; kt++) {
        CP_WAIT1();
        __syncthreads();
        if (kt + 2 < NT) issue(kt + 2);
        CP_COMMIT();

        const uint32_t stage = sm0 + (kt % NSTG) * STAGE_BYTES;
        const uint32_t aBase = stage + aOff;
        const uint32_t bBase = stage + bOff;
#pragma unroll
        for (int kc = 0; kc < 4; kc++) {
            uint32_t a[4][4], b2[2][4];
#pragma unroll
            for (int tm = 0; tm < 4; tm++)
                ldsm_x4(a[tm], aBase + (uint32_t)(tm * 16 * PITCH) * 2 + kc * 32);
#pragma unroll
            for (int tp = 0; tp < 2; tp++)
                ldsm_x4(b2[tp], bBase + (uint32_t)(tp * 16 * PITCH) * 2 + kc * 32);
#pragma unroll
            for (int tm = 0; tm < 4; tm++)
#pragma unroll
                for (int tn = 0; tn < 4; tn++)
                    MMA_F16(acc[tm][tn], a[tm], (&b2[tn >> 1][(tn & 1) * 2]));
        }
    }

    __syncthreads();
#pragma unroll
    for (int tm = 0; tm < 4; tm++) {
#pragma unroll
        for (int tn = 0; tn < 4; tn++) {
            int row = m0 + wm + tm * 16 + (lane >> 2);
            int col = n0 + wn + tn * 8 + 2 * (lane & 3);
            if constexpr (sizeof(OT) == 2) {
                *(__half2*)((__half*)C + (size_t)row * N + col) =
                    __floats2half2_rn(acc[tm][tn][0], acc[tm][tn][1]);
                *(__half2*)((__half*)C + (size_t)(row + 8) * N + col) =
                    __floats2half2_rn(acc[tm][tn][2], acc[tm][tn][3]);
            } else {
                *(float2*)((float*)C + (size_t)row * N + col) =
                    make_float2(acc[tm][tn][0], acc[tm][tn][1]);
                *(float2*)((float*)C + (size_t)(row + 8) * N + col) =
                    make_float2(acc[tm][tn][2], acc[tm][tn][3]);
            }
        }
    }
}

// ===========================================================================
// O-projection GEMM over HALF the rows (the (b,s) rows with s in the given
// half of the sequence): m0 = half*1024 + (y&7)*128 + (y>>3)*2048, grid y=16.
// fp32 output. Same body/config as gemm_f16 otherwise.
// ===========================================================================
__global__ __launch_bounds__(256, 2) void gemm_f16o(
    const __half* __restrict__ A, const __half* __restrict__ Bt,
    float* __restrict__ C, int N, int K, int half)
{
    extern __shared__ __half smh[];
    const int tid = threadIdx.x;
    const int warp = tid >> 5, lane = tid & 31;
    const int wm = (warp >> 2) * 64, wn = (warp & 3) * 32;
    const int m0 = half * 1024 + (blockIdx.y & 7) * BM + (blockIdx.y >> 3) * 2048;
    const int n0 = blockIdx.x * BN;
    const int NT = K / BKH;

    const int sel = lane >> 3, rr = lane & 7;
    const uint32_t sm0 = (uint32_t)__cvta_generic_to_shared(smh);
    const uint32_t aOff = ((uint32_t)(wm + (sel & 1) * 8 + rr) * PITCH + (sel >> 1) * 8) * 2;
    const uint32_t bOff = (uint32_t)(128 * PITCH) * 2 +
                          ((uint32_t)(wn + (sel >> 1) * 8 + rr) * PITCH + (sel & 1) * 8) * 2;

    float acc[4][4][4];
#pragma unroll
    for (int i = 0; i < 4; i++)
#pragma unroll
        for (int j = 0; j < 4; j++)
#pragma unroll
            for (int x = 0; x < 4; x++) acc[i][j][x] = 0.f;

    auto issue = [&](int kt) {
        __half* st = smh + (kt % NSTG) * STAGE_HALF;
        __half* As = st;
        __half* Bs = st + 128 * PITCH;
        const __half* Ag = A + (size_t)m0 * K + kt * BKH;
        const __half* Bg = Bt + (size_t)n0 * K + kt * BKH;
#pragma unroll
        for (int i = 0; i < 4; i++) {
            int idx = tid + i * 256;
            int r = idx >> 3, ch = idx & 7;
            cpasync16(As + r * PITCH + ch * 8, Ag + (size_t)r * K + ch * 8);
        }
#pragma unroll
        for (int i = 0; i < 4; i++) {
            int idx = tid + i * 256;
            int r = idx >> 3, ch = idx & 7;
            cpasync16(Bs + r * PITCH + ch * 8, Bg + (size_t)r * K + ch * 8);
        }
    };

    issue(0); CP_COMMIT();
    issue(1); CP_COMMIT();

    for (int kt = 0; kt < NT; kt++) {
        CP_WAIT1();
        __syncthreads();
        if (kt + 2 < NT) issue(kt + 2);
        CP_COMMIT();

        const uint32_t stage = sm0 + (kt % NSTG) * STAGE_BYTES;
        const uint32_t aBase = stage + aOff;
        const uint32_t bBase = stage + bOff;
#pragma unroll
        for (int kc = 0; kc < 4; kc++) {
            uint32_t a[4][4], b2[2][4];
#pragma unroll
            for (int tm = 0; tm < 4; tm++)
                ldsm_x4(a[tm], aBase + (uint32_t)(tm * 16 * PITCH) * 2 + kc * 32);
#pragma unroll
            for (int tp = 0; tp < 2; tp++)
                ldsm_x4(b2[tp], bBase + (uint32_t)(tp * 16 * PITCH) * 2 + kc * 32);
#pragma unroll
            for (int tm = 0; tm < 4; tm++)
#pragma unroll
                for (int tn = 0; tn < 4; tn++)
                    MMA_F16(acc[tm][tn], a[tm], (&b2[tn >> 1][(tn & 1) * 2]));
        }
    }

    __syncthreads();
#pragma unroll
    for (int tm = 0; tm < 4; tm++) {
#pragma unroll
        for (int tn = 0; tn < 4; tn++) {
            int row = m0 + wm + tm * 16 + (lane >> 2);
            int col = n0 + wn + tn * 8 + 2 * (lane & 3);
            *(float2*)(C + (size_t)row * N + col) =
                make_float2(acc[tm][tn][0], acc[tm][tn][1]);
            *(float2*)(C + (size_t)(row + 8) * N + col) =
                make_float2(acc[tm][tn][2], acc[tm][tn][3]);
        }
    }
}

// ---------------------------------------------------------------------------
// Prep kernels
// ---------------------------------------------------------------------------
__global__ __launch_bounds__(256) void to_half(const float4* __restrict__ src,
                                               __half* __restrict__ dst, int n4)
{
    int i = blockIdx.x * 256 + threadIdx.x;
    if (i < n4) {
        float4 v = src[i];
        __half2* d = (__half2*)(dst + (size_t)i * 4);
        d[0] = __floats2half2_rn(v.x, v.y);
        d[1] = __floats2half2_rn(v.z, v.w);
    }
}

__global__ __launch_bounds__(256) void transpose_half(
    const float* __restrict__ src, __half* __restrict__ dst, int R, int C)
{
    __shared__ float t[32][33];
    const int bx = blockIdx.x * 32;
    const int by = blockIdx.y * 32;
    const int x = threadIdx.x & 31;
    const int y0 = (threadIdx.x >> 5) * 4;
#pragma unroll
    for (int j = 0; j < 4; j++)
        t[y0 + j][x] = src[(size_t)(by + y0 + j) * C + bx + x];
    __syncthreads();
#pragma unroll
    for (int j = 0; j < 4; j++)
        dst[(size_t)(bx + y0 + j) * R + by + x] = __float2half_rn(t[x][y0 + j]);
}

// V slice of fused QKV fp16 (row stride NQKV) -> Vt fp16 [b][kv][d][s]
__global__ __launch_bounds__(256) void transpose_vt(
    const __half* __restrict__ v, __half* __restrict__ vt)
{
    __shared__ __half t[32][34];
    const int bkv = blockIdx.z;
    const int b = bkv >> 2, kv = bkv & 3;
    const int s0 = blockIdx.y * 32;
    const int d0 = blockIdx.x * 32;
    const int x = threadIdx.x & 31;
    const int y0 = (threadIdx.x >> 5) * 4;
#pragma unroll
    for (int j = 0; j < 4; j++)
        t[y0 + j][x] = v[(size_t)(b * Sc + s0 + y0 + j) * NQKV + kv * HDc + d0 + x];
    __syncthreads();
#pragma unroll
    for (int j = 0; j < 4; j++)
        vt[(size_t)(bkv * HDc + d0 + y0 + j) * Sc + s0 + x] = t[x][y0 + j];
}

// ---------------------------------------------------------------------------
// RMSNorm + RoPE, warp-per-row (champion config from round 15).
// ---------------------------------------------------------------------------
__global__ __launch_bounds__(256) void rmsnorm_rope_qk(
    const __half* __restrict__ qkv, __half* __restrict__ qout,
    __half* __restrict__ kout, const float* __restrict__ qw,
    const float* __restrict__ kw, const int* __restrict__ pos_ids)
{
    const int M = Bc * Sc;
    int row = blockIdx.x * 8 + (threadIdx.x >> 5);
    const int lane = threadIdx.x & 31;
    const bool isQ = row < M * Hc;
    int nh, colbase;
    const float* w;
    __half* outp;
    float oscale;
    if (isQ) { nh = Hc; colbase = 0; w = qw; outp = qout;
               oscale = 0.0625f * 1.44269504088896f; }
    else     { row -= M * Hc; nh = KVc; colbase = Hc * HDc; w = kw; outp = kout; oscale = 1.0f; }

    const int head = row % nh;
    const int bs = row / nh;
    const int s = bs % Sc, b = bs / Sc;
    const int d0 = lane * 4;

    const __half* src = qkv + (size_t)bs * NQKV + colbase + head * HDc;
    const __half2* pLo = (const __half2*)(src + d0);
    const __half2* pHi = (const __half2*)(src + 128 + d0);

    float v[4], z[4];
    {
        float2 a = __half22float2(pLo[0]);
        float2 c = __half22float2(pLo[1]);
        v[0] = a.x; v[1] = a.y; v[2] = c.x; v[3] = c.y;
        float2 e = __half22float2(pHi[0]);
        float2 f = __half22float2(pHi[1]);
        z[0] = e.x; z[1] = e.y; z[2] = f.x; z[3] = f.y;
    }

    float sq = v[0]*v[0] + v[1]*v[1] + v[2]*v[2] + v[3]*v[3]
             + z[0]*z[0] + z[1]*z[1] + z[2]*z[2] + z[3]*z[3];
#pragma unroll
    for (int o = 16; o; o >>= 1) sq += __shfl_xor_sync(0xffffffffu, sq, o);
    const float rstd = rsqrtf(sq * (1.0f / 256.0f) + 1e-6f);

    const float p = (float)pos_ids[s];
    __half* dst = outp + ((size_t)(b * nh + head) * Sc + s) * HDc;
    float outLo[4], outHi[4];
#pragma unroll
    for (int i = 0; i < 4; i++) {
        float y = v[i] * rstd * (1.0f + w[d0 + i]);
        float zz = z[i] * rstd * (1.0f + w[128 + d0 + i]);
        float inv_freq = exp2f((float)(d0 + i) * (-13.2877123795494f / 128.0f));
        float sv, cv;
        __sincosf(p * inv_freq, &sv, &cv);
        outLo[i] = (y * cv - zz * sv) * oscale;
        outHi[i] = (zz * cv + y * sv) * oscale;
    }
    ((__half2*)(dst + d0))[0]       = __floats2half2_rn(outLo[0], outLo[1]);
    ((__half2*)(dst + d0))[1]       = __floats2half2_rn(outLo[2], outLo[3]);
    ((__half2*)(dst + 128 + d0))[0] = __floats2half2_rn(outHi[0], outHi[1]);
    ((__half2*)(dst + 128 + d0))[1] = __floats2half2_rn(outHi[2], outHi[3]);
}

// ===========================================================================
// FA2-style tensor-core flash attention (champion config) with qt_base so the
// q-tile range can be split across two launches.
// ===========================================================================
#define FQP 264
#define FVP 72
#define F_KS (128 * FQP)
#define F_VS (F_KS + 2 * 64 * FQP)
#define FLASH_SMEM ((F_VS + 2 * 256 * FVP) * 2)

__global__ __launch_bounds__(256, 1) void flash_attn_tc(
    const __half* __restrict__ qh, const __half* __restrict__ kh,
    const __half* __restrict__ vt, __half* __restrict__ ob, int qt_base)
{
    extern __shared__ __half sm[];
    __half* Qs  = sm;
    __half* Ks0 = sm + F_KS;
    __half* Vs0 = sm + F_VS;

    const int qt = qt_base + gridDim.x - 1 - blockIdx.x;   // heavy tiles first
    const int q0 = qt * 128;
    const int h = blockIdx.y, b = blockIdx.z;
    const int kvh = h >> 2;
    const int tid = threadIdx.x;
    const int w = tid >> 5, lane = tid & 31;
    const int lr = lane >> 2, lc = lane & 3;
    const int sel = lane >> 3, rr = lane & 7;

    const __half* Qg = qh + ((size_t)(b * Hc + h) * Sc + q0) * HDc;
    const __half* Kg = kh + ((size_t)(b * KVc + kvh) * Sc) * HDc;
    const __half* Vg = vt + ((size_t)(b * KVc + kvh) * HDc) * Sc;

    auto issue_kv = [&](int t, int buf) {
        const int j0 = t * 64;
        __half* Kd = Ks0 + buf * 64 * FQP;
        __half* Vd = Vs0 + buf * 256 * FVP;
#pragma unroll
        for (int i = 0; i < 8; i++) {
            int idx = tid + i * 256;
            int r = idx >> 5, ch = idx & 31;
            cpasync16(Kd + r * FQP + ch * 8, Kg + (size_t)(j0 + r) * HDc + ch * 8);
        }
#pragma unroll
        for (int i = 0; i < 8; i++) {
            int idx = tid + i * 256;
            int r = idx >> 3, ch = idx & 7;
            cpasync16(Vd + r * FVP + ch * 8, Vg + (size_t)r * Sc + j0 + ch * 8);
        }
    };

#pragma unroll
    for (int i = 0; i < 16; i++) {
        int idx = tid + i * 256;
        int r = idx >> 5, ch = idx & 31;
        cpasync16(Qs + r * FQP + ch * 8, Qg + (size_t)r * HDc + ch * 8);
    }
    issue_kv(0, 0);
    CP_COMMIT();

    const uint32_t smb = (uint32_t)__cvta_generic_to_shared(sm);
    const uint32_t qA   = smb + ((uint32_t)(w * 16 + (sel & 1) * 8 + rr) * FQP + (sel >> 1) * 8) * 2;
    const uint32_t kOff = ((uint32_t)((sel >> 1) * 8 + rr) * FQP + (sel & 1) * 8) * 2;
    const uint32_t vOff = ((uint32_t)((sel >> 1) * 8 + rr) * FVP + (sel & 1) * 8) * 2;

    float oacc[32][4];
#pragma unroll
    for (int i = 0; i < 32; i++)
#pragma unroll
        for (int j = 0; j < 4; j++) oacc[i][j] = 0.f;
    float m0v = -1e30f, m1v = -1e30f, l0 = 0.f, l1 = 0.f;

    const int qg0 = q0 + w * 16 + lr;
    const int qg1 = qg0 + 8;
    const int qmaxw = q0 + w * 16 + 15;
    const int ntiles = q0 / 64 + 2;

    for (int t = 0; t < ntiles; t++) {
        CP_WAIT0();
        __syncthreads();
        if (t + 1 < ntiles) { issue_kv(t + 1, (t + 1) & 1); CP_COMMIT(); }
        const int j0 = t * 64;

        if (j0 <= qmaxw) {
            const uint32_t kB = smb + (uint32_t)(F_KS + (t & 1) * 64 * FQP) * 2 + kOff;
            const uint32_t vB = smb + (uint32_t)(F_VS + (t & 1) * 256 * FVP) * 2 + vOff;

            float sacc[8][4];
#pragma unroll
            for (int i = 0; i < 8; i++)
#pragma unroll
                for (int j = 0; j < 4; j++) sacc[i][j] = 0.f;
#pragma unroll
            for (int kc = 0; kc < 16; kc++) {
                uint32_t a[4];
                ldsm_x4(a, qA + kc * 32);
#pragma unroll
                for (int tp = 0; tp < 4; tp++) {
                    uint32_t bb[4];
                    ldsm_x4(bb, kB + (uint32_t)(tp * 16 * FQP) * 2 + kc * 32);
                    MMA_F16(sacc[2 * tp], a, (&bb[0]));
                    MMA_F16(sacc[2 * tp + 1], a, (&bb[2]));
                }
            }

            if (j0 + 63 > q0 + w * 16) {
#pragma unroll
                for (int nf = 0; nf < 8; nf++) {
                    int j = j0 + 8 * nf + 2 * lc;
                    if (j > qg0)     sacc[nf][0] = -1e30f;
                    if (j + 1 > qg0) sacc[nf][1] = -1e30f;
                    if (j > qg1)     sacc[nf][2] = -1e30f;
                    if (j + 1 > qg1) sacc[nf][3] = -1e30f;
                }
            }

            float mx0 = -1e30f, mx1 = -1e30f;
#pragma unroll
            for (int nf = 0; nf < 8; nf++) {
                mx0 = fmaxf(mx0, fmaxf(sacc[nf][0], sacc[nf][1]));
                mx1 = fmaxf(mx1, fmaxf(sacc[nf][2], sacc[nf][3]));
            }
            mx0 = fmaxf(mx0, __shfl_xor_sync(0xffffffffu, mx0, 1));
            mx0 = fmaxf(mx0, __shfl_xor_sync(0xffffffffu, mx0, 2));
            mx1 = fmaxf(mx1, __shfl_xor_sync(0xffffffffu, mx1, 1));
            mx1 = fmaxf(mx1, __shfl_xor_sync(0xffffffffu, mx1, 2));
            float mn0 = fmaxf(m0v, mx0), mn1 = fmaxf(m1v, mx1);
            float alpha0 = ex2(m0v - mn0);
            float alpha1 = ex2(m1v - mn1);
            m0v = mn0; m1v = mn1;

            float ps0 = 0.f, ps1 = 0.f;
#pragma unroll
            for (int nf = 0; nf < 8; nf++) {
                sacc[nf][0] = ex2(sacc[nf][0] - mn0);
                sacc[nf][1] = ex2(sacc[nf][1] - mn0);
                sacc[nf][2] = ex2(sacc[nf][2] - mn1);
                sacc[nf][3] = ex2(sacc[nf][3] - mn1);
                ps0 += sacc[nf][0] + sacc[nf][1];
                ps1 += sacc[nf][2] + sacc[nf][3];
            }
            ps0 += __shfl_xor_sync(0xffffffffu, ps0, 1);
            ps0 += __shfl_xor_sync(0xffffffffu, ps0, 2);
            ps1 += __shfl_xor_sync(0xffffffffu, ps1, 1);
            ps1 += __shfl_xor_sync(0xffffffffu, ps1, 2);
            l0 = l0 * alpha0 + ps0;
            l1 = l1 * alpha1 + ps1;

#pragma unroll
            for (int nf = 0; nf < 32; nf++) {
                oacc[nf][0] *= alpha0; oacc[nf][1] *= alpha0;
                oacc[nf][2] *= alpha1; oacc[nf][3] *= alpha1;
            }

#pragma unroll
            for (int kc = 0; kc < 4; kc++) {
                uint32_t pa[4];
                pa[0] = packh2(sacc[2 * kc][0],     sacc[2 * kc][1]);
                pa[1] = packh2(sacc[2 * kc][2],     sacc[2 * kc][3]);
                pa[2] = packh2(sacc[2 * kc + 1][0], sacc[2 * kc + 1][1]);
                pa[3] = packh2(sacc[2 * kc + 1][2], sacc[2 * kc + 1][3]);
#pragma unroll
                for (int tp = 0; tp < 16; tp++) {
                    uint32_t bb[4];
                    ldsm_x4(bb, vB + (uint32_t)(tp * 16 * FVP) * 2 + kc * 32);
                    MMA_F16(oacc[2 * tp], pa, (&bb[0]));
                    MMA_F16(oacc[2 * tp + 1], pa, (&bb[2]));
                }
            }
        }
    }

    const float inv0 = 1.f / l0;
    const float inv1 = 1.f / l1;
#pragma unroll
    for (int nf = 0; nf < 32; nf++) {
        int col = h * HDc + 8 * nf + 2 * lc;
        size_t r0a = (size_t)(b * Sc + q0 + w * 16 + lr) * (Hc * HDc) + col;
        size_t r1a = (size_t)(b * Sc + q0 + w * 16 + lr + 8) * (Hc * HDc) + col;
        *(__half2*)(ob + r0a) = __floats2half2_rn(oacc[nf][0] * inv0, oacc[nf][1] * inv0);
        *(__half2*)(ob + r1a) = __floats2half2_rn(oacc[nf][2] * inv1, oacc[nf][3] * inv1);
    }
}

// ---------------------------------------------------------------------------
extern "C" void kernel_launch(void* const* d_in, const int* in_sizes, int n_in,
                              void* d_out, int out_size)
{
    const float* hidden = (const float*)d_in[0];
    const float* Wq = (const float*)d_in[1];
    const float* Wk = (const float*)d_in[2];
    const float* Wv = (const float*)d_in[3];
    const float* Wo = (const float*)d_in[4];
    const float* qw = (const float*)d_in[5];
    const float* kw = (const float*)d_in[6];
    const int*  pos = (const int*)d_in[7];
    float* out = (float*)d_out;

    __half *qkvh, *qhh, *khh, *vth, *ah, *hh, *wqkvT, *woT;
    cudaGetSymbolAddress((void**)&qkvh, g_qkvh);
    cudaGetSymbolAddress((void**)&qhh, g_qh);
    cudaGetSymbolAddress((void**)&khh, g_kh);
    cudaGetSymbolAddress((void**)&vth, g_vt);
    cudaGetSymbolAddress((void**)&ah, g_attn_h);
    cudaGetSymbolAddress((void**)&hh, g_hh);
    cudaGetSymbolAddress((void**)&wqkvT, g_wqkvT);
    cudaGetSymbolAddress((void**)&woT, g_woT);

    const int M = Bc * Sc;           // 4096
    const int NQ = Hc * HDc;         // 4096
    const int NKV = KVc * HDc;       // 1024

    cudaFuncSetAttribute(gemm_f16<__half>, cudaFuncAttributeMaxDynamicSharedMemorySize, GEMM_SMEM);
    cudaFuncSetAttribute(gemm_f16o, cudaFuncAttributeMaxDynamicSharedMemorySize, GEMM_SMEM);
    cudaFuncSetAttribute(flash_attn_tc, cudaFuncAttributeMaxDynamicSharedMemorySize, FLASH_SMEM);

    // Side streams + events for capturable fork/join
    cudaStream_t s1, s2;
    cudaStreamCreateWithFlags(&s1, cudaStreamNonBlocking);
    cudaStreamCreateWithFlags(&s2, cudaStreamNonBlocking);
    cudaEvent_t evRoot, evKV, evQ, evWo, evG, evVt, evFL, evOL;
    cudaEventCreateWithFlags(&evRoot, cudaEventDisableTiming);
    cudaEventCreateWithFlags(&evKV, cudaEventDisableTiming);
    cudaEventCreateWithFlags(&evQ, cudaEventDisableTiming);
    cudaEventCreateWithFlags(&evWo, cudaEventDisableTiming);
    cudaEventCreateWithFlags(&evG, cudaEventDisableTiming);
    cudaEventCreateWithFlags(&evVt, cudaEventDisableTiming);
    cudaEventCreateWithFlags(&evFL, cudaEventDisableTiming);
    cudaEventCreateWithFlags(&evOL, cudaEventDisableTiming);

    cudaEventRecord(evRoot, 0);
    cudaStreamWaitEvent(s1, evRoot, 0);
    cudaStreamWaitEvent(s2, evRoot, 0);

    // main: hidden -> fp16
    {
        int n4 = M * Dc / 4;
        to_half<<<(n4 + 255) / 256, 256>>>((const float4*)hidden, hh, n4);
    }
    // s1: Wk, Wv, then Wo
    transpose_half<<<dim3(NKV / 32, Dc / 32), 256, 0, s1>>>(Wk, wqkvT + (size_t)NQ * Dc, Dc, NKV);
    transpose_half<<<dim3(NKV / 32, Dc / 32), 256, 0, s1>>>(Wv, wqkvT + (size_t)(NQ + NKV) * Dc, Dc, NKV);
    cudaEventRecord(evKV, s1);
    transpose_half<<<dim3(Dc / 32, NQ / 32), 256, 0, s1>>>(Wo, woT, NQ, Dc);
    cudaEventRecord(evWo, s1);
    // s2: Wq
    transpose_half<<<dim3(NQ / 32, Dc / 32), 256, 0, s2>>>(Wq, wqkvT, Dc, NQ);
    cudaEventRecord(evQ, s2);

    // join -> fused QKV projection
    cudaStreamWaitEvent(0, evKV, 0);
    cudaStreamWaitEvent(0, evQ, 0);
    gemm_f16<__half><<<dim3(NQKV / BN, M / BM), 256, GEMM_SMEM>>>(hh, wqkvT, qkvh, M, NQKV, Dc);

    // fork: transpose_vt (s1) parallel with rmsnorm (main)
    cudaEventRecord(evG, 0);
    cudaStreamWaitEvent(s1, evG, 0);
    transpose_vt<<<dim3(HDc / 32, Sc / 32, Bc * KVc), 256, 0, s1>>>(qkvh + NQ + NKV, vth);
    cudaEventRecord(evVt, s1);
    rmsnorm_rope_qk<<<M * (Hc + KVc) / 8, 256>>>(qkvh, qhh, khh, qw, kw, pos);

    // flash LOW half (q0 < 1024; cheap) on main
    cudaStreamWaitEvent(0, evVt, 0);
    flash_attn_tc<<<dim3(8, Hc, Bc), 256, FLASH_SMEM>>>(qhh, khh, vth, ah, 0);
    cudaEventRecord(evFL, 0);

    // s1: O-projection over the low-s rows, overlapping flash HIGH on main
    cudaStreamWaitEvent(s1, evFL, 0);   // s1 already ran Wo in-order
    gemm_f16o<<<dim3(Dc / BN, 16), 256, GEMM_SMEM, s1>>>(ah, woT, out, Dc, NQ, 0);
    cudaEventRecord(evOL, s1);

    // flash HIGH half (q0 >= 1024; heavy) on main
    flash_attn_tc<<<dim3(8, Hc, Bc), 256, FLASH_SMEM>>>(qhh, khh, vth, ah, 8);

    // O-projection over the high-s rows on main (Wo already joined via evWo path on s1;
    // main needs its own Wo dependency)
    cudaStreamWaitEvent(0, evWo, 0);
    gemm_f16o<<<dim3(Dc / BN, 16), 256, GEMM_SMEM>>>(ah, woT, out, Dc, NQ, 1);

    // final join so the captured graph ends after BOTH O halves
    cudaStreamWaitEvent(0, evOL, 0);

    cudaEventDestroy(evRoot);
    cudaEventDestroy(evKV);
    cudaEventDestroy(evQ);
    cudaEventDestroy(evWo);
    cudaEventDestroy(evG);
    cudaEventDestroy(evVt);
    cudaEventDestroy(evFL);
    cudaEventDestroy(evOL);
    cudaStreamDestroy(s1);
    cudaStreamDestroy(s2);
}

// round 17
// speedup vs baseline: 1.0314x; 1.0314x over previous
#include <cuda_runtime.h>
#include <cuda_fp16.h>
#include <cstdint>

// Problem constants (Gemma4 attention): B=2, S=2048, D=2048, H=16, KV=4, HD=256
#define Bc 2
#define Sc 2048
#define Dc 2048
#define Hc 16
#define KVc 4
#define HDc 256
#define NQKV 6144   // H*HD + 2*KV*HD

// Scratch (__device__ globals; no cudaMalloc allowed)
__device__ __half g_qkvh[(size_t)Bc * Sc * NQKV];        // fused QKV out fp16
__device__ __half g_qh[(size_t)Bc * Hc * Sc * HDc];      // [b][h][s][d] (scaled 1/16*log2e)
__device__ __half g_kh[(size_t)Bc * KVc * Sc * HDc];     // [b][kv][s][d]
__device__ __half g_vt[(size_t)Bc * KVc * HDc * Sc];     // [b][kv][d][s]
__device__ __half g_attn_h[(size_t)Bc * Sc * Hc * HDc];  // [b,s][h*HD] fp16
__device__ __half g_hh[(size_t)Bc * Sc * Dc];            // hidden fp16
__device__ __half g_wqkvT[(size_t)NQKV * Dc];            // [6144][2048] fp16
__device__ __half g_woT[(size_t)Dc * (Hc * HDc)];        // [2048][4096]

// ===========================================================================
// Common PTX helpers
// ===========================================================================
__device__ __forceinline__ void cpasync16(const void* smem_dst, const void* gsrc) {
    uint32_t d = (uint32_t)__cvta_generic_to_shared(smem_dst);
    asm volatile("cp.async.cg.shared.global [%0], [%1], 16;" :: "r"(d), "l"(gsrc));
}
#define CP_COMMIT() asm volatile("cp.async.commit_group;" ::: "memory")
#define CP_WAIT0()  asm volatile("cp.async.wait_group 0;" ::: "memory")
#define CP_WAIT1()  asm volatile("cp.async.wait_group 1;" ::: "memory")

#define MMA_F16(d, a, b) \
    asm volatile("mma.sync.aligned.m16n8k16.row.col.f32.f16.f16.f32 " \
                 "{%0,%1,%2,%3}, {%4,%5,%6,%7}, {%8,%9}, {%0,%1,%2,%3};" \
                 : "+f"(d[0]), "+f"(d[1]), "+f"(d[2]), "+f"(d[3]) \
                 : "r"(a[0]), "r"(a[1]), "r"(a[2]), "r"(a[3]), \
                   "r"(b[0]), "r"(b[1]))

__device__ __forceinline__ void ldsm_x4(uint32_t* r, uint32_t saddr) {
    asm volatile("ldmatrix.sync.aligned.m8n8.x4.shared.b16 {%0,%1,%2,%3}, [%4];"
                 : "=r"(r[0]), "=r"(r[1]), "=r"(r[2]), "=r"(r[3]) : "r"(saddr));
}
__device__ __forceinline__ uint32_t packh2(float a, float b) {
    __half2 h = __floats2half2_rn(a, b);
    return *(uint32_t*)&h;
}
__device__ __forceinline__ float ex2(float x) {
    float r;
    asm("ex2.approx.ftz.f32 %0, %1;" : "=f"(r) : "f"(x));
    return r;
}

// ===========================================================================
// fp16 mma.sync GEMM, ldmatrix fragments, 3-stage cp.async pipeline.
// CTA 128x128, 8 warps (2x4), warp tile 64x32, 2 CTAs/SM. Templated output.
// ===========================================================================
#define BM 128
#define BN 128
#define BKH 64
#define PITCH 72
#define NSTG 3
#define STAGE_HALF (2 * 128 * PITCH)
#define STAGE_BYTES (STAGE_HALF * 2)
#define GEMM_SMEM (NSTG * STAGE_BYTES)    // 110592

template <typename OT>
__global__ __launch_bounds__(256, 2) void gemm_f16(
    const __half* __restrict__ A, const __half* __restrict__ Bt,
    OT* __restrict__ C, int M, int N, int K)
{
    extern __shared__ __half smh[];
    const int tid = threadIdx.x;
    const int warp = tid >> 5, lane = tid & 31;
    const int wm = (warp >> 2) * 64, wn = (warp & 3) * 32;
    const int m0 = blockIdx.y * BM, n0 = blockIdx.x * BN;
    const int NT = K / BKH;

    const int sel = lane >> 3, rr = lane & 7;
    const uint32_t sm0 = (uint32_t)__cvta_generic_to_shared(smh);
    const uint32_t aOff = ((uint32_t)(wm + (sel & 1) * 8 + rr) * PITCH + (sel >> 1) * 8) * 2;
    const uint32_t bOff = (uint32_t)(128 * PITCH) * 2 +
                          ((uint32_t)(wn + (sel >> 1) * 8 + rr) * PITCH + (sel & 1) * 8) * 2;

    float acc[4][4][4];
#pragma unroll
    for (int i = 0; i < 4; i++)
#pragma unroll
        for (int j = 0; j < 4; j++)
#pragma unroll
            for (int x = 0; x < 4; x++) acc[i][j][x] = 0.f;

    auto issue = [&](int kt) {
        __half* st = smh + (kt % NSTG) * STAGE_HALF;
        __half* As = st;
        __half* Bs = st + 128 * PITCH;
        const __half* Ag = A + (size_t)m0 * K + kt * BKH;
        const __half* Bg = Bt + (size_t)n0 * K + kt * BKH;
#pragma unroll
        for (int i = 0; i < 4; i++) {
            int idx = tid + i * 256;
            int r = idx >> 3, ch = idx & 7;
            cpasync16(As + r * PITCH + ch * 8, Ag + (size_t)r * K + ch * 8);
        }
#pragma unroll
        for (int i = 0; i < 4; i++) {
            int idx = tid + i * 256;
            int r = idx >> 3, ch = idx & 7;
            cpasync16(Bs + r * PITCH + ch * 8, Bg + (size_t)r * K + ch * 8);
        }
    };

    issue(0); CP_COMMIT();
    issue(1); CP_COMMIT();

    for (int kt = 0; kt < NT; kt++) {
        CP_WAIT1();
        __syncthreads();
        if (kt + 2 < NT) issue(kt + 2);
        CP_COMMIT();

        const uint32_t stage = sm0 + (kt % NSTG) * STAGE_BYTES;
        const uint32_t aBase = stage + aOff;
        const uint32_t bBase = stage + bOff;
#pragma unroll
        for (int kc = 0; kc < 4; kc++) {
            uint32_t a[4][4], b2[2][4];
#pragma unroll
            for (int tm = 0; tm < 4; tm++)
                ldsm_x4(a[tm], aBase + (uint32_t)(tm * 16 * PITCH) * 2 + kc * 32);
#pragma unroll
            for (int tp = 0; tp < 2; tp++)
                ldsm_x4(b2[tp], bBase + (uint32_t)(tp * 16 * PITCH) * 2 + kc * 32);
#pragma unroll
            for (int tm = 0; tm < 4; tm++)
#pragma unroll
                for (int tn = 0; tn < 4; tn++)
                    MMA_F16(acc[tm][tn], a[tm], (&b2[tn >> 1][(tn & 1) * 2]));
        }
    }

    __syncthreads();
#pragma unroll
    for (int tm = 0; tm < 4; tm++) {
#pragma unroll
        for (int tn = 0; tn < 4; tn++) {
            int row = m0 + wm + tm * 16 + (lane >> 2);
            int col = n0 + wn + tn * 8 + 2 * (lane & 3);
            if constexpr (sizeof(OT) == 2) {
                *(__half2*)((__half*)C + (size_t)row * N + col) =
                    __floats2half2_rn(acc[tm][tn][0], acc[tm][tn][1]);
                *(__half2*)((__half*)C + (size_t)(row + 8) * N + col) =
                    __floats2half2_rn(acc[tm][tn][2], acc[tm][tn][3]);
            } else {
                *(float2*)((float*)C + (size_t)row * N + col) =
                    make_float2(acc[tm][tn][0], acc[tm][tn][1]);
                *(float2*)((float*)C + (size_t)(row + 8) * N + col) =
                    make_float2(acc[tm][tn][2], acc[tm][tn][3]);
            }
        }
    }
}

// ---------------------------------------------------------------------------
// Prep kernels
// ---------------------------------------------------------------------------
__global__ __launch_bounds__(256) void to_half(const float4* __restrict__ src,
                                               __half* __restrict__ dst, int n4)
{
    int i = blockIdx.x * 256 + threadIdx.x;
    if (i < n4) {
        float4 v = src[i];
        __half2* d = (__half2*)(dst + (size_t)i * 4);
        d[0] = __floats2half2_rn(v.x, v.y);
        d[1] = __floats2half2_rn(v.z, v.w);
    }
}

__global__ __launch_bounds__(256) void transpose_half(
    const float* __restrict__ src, __half* __restrict__ dst, int R, int C)
{
    __shared__ float t[32][33];
    const int bx = blockIdx.x * 32;
    const int by = blockIdx.y * 32;
    const int x = threadIdx.x & 31;
    const int y0 = (threadIdx.x >> 5) * 4;
#pragma unroll
    for (int j = 0; j < 4; j++)
        t[y0 + j][x] = src[(size_t)(by + y0 + j) * C + bx + x];
    __syncthreads();
#pragma unroll
    for (int j = 0; j < 4; j++)
        dst[(size_t)(bx + y0 + j) * R + by + x] = __float2half_rn(t[x][y0 + j]);
}

// V slice of fused QKV fp16 (row stride NQKV) -> Vt fp16 [b][kv][d][s]
__global__ __launch_bounds__(256) void transpose_vt(
    const __half* __restrict__ v, __half* __restrict__ vt)
{
    __shared__ __half t[32][34];
    const int bkv = blockIdx.z;
    const int b = bkv >> 2, kv = bkv & 3;
    const int s0 = blockIdx.y * 32;
    const int d0 = blockIdx.x * 32;
    const int x = threadIdx.x & 31;
    const int y0 = (threadIdx.x >> 5) * 4;
#pragma unroll
    for (int j = 0; j < 4; j++)
        t[y0 + j][x] = v[(size_t)(b * Sc + s0 + y0 + j) * NQKV + kv * HDc + d0 + x];
    __syncthreads();
#pragma unroll
    for (int j = 0; j < 4; j++)
        vt[(size_t)(bkv * HDc + d0 + y0 + j) * Sc + s0 + x] = t[x][y0 + j];
}

// ---------------------------------------------------------------------------
// RMSNorm + RoPE, warp-per-row. Lane l owns d = 4l..4l+3 AND d+128..d+131,
// so the RoPE partner is in-lane: no smem, no block syncs, 5-shfl reduction.
// Q rows get oscale = (1/16)*log2(e) (base-2 softmax domain).
// ---------------------------------------------------------------------------
__global__ __launch_bounds__(256) void rmsnorm_rope_qk(
    const __half* __restrict__ qkv, __half* __restrict__ qout,
    __half* __restrict__ kout, const float* __restrict__ qw,
    const float* __restrict__ kw, const int* __restrict__ pos_ids)
{
    const int M = Bc * Sc;
    int row = blockIdx.x * 8 + (threadIdx.x >> 5);
    const int lane = threadIdx.x & 31;
    const bool isQ = row < M * Hc;
    int nh, colbase;
    const float* w;
    __half* outp;
    float oscale;
    if (isQ) { nh = Hc; colbase = 0; w = qw; outp = qout;
               oscale = 0.0625f * 1.44269504088896f; }
    else     { row -= M * Hc; nh = KVc; colbase = Hc * HDc; w = kw; outp = kout; oscale = 1.0f; }

    const int head = row % nh;
    const int bs = row / nh;
    const int s = bs % Sc, b = bs / Sc;
    const int d0 = lane * 4;

    const __half* src = qkv + (size_t)bs * NQKV + colbase + head * HDc;
    const __half2* pLo = (const __half2*)(src + d0);
    const __half2* pHi = (const __half2*)(src + 128 + d0);

    float v[4], z[4];
    {
        float2 a = __half22float2(pLo[0]);
        float2 c = __half22float2(pLo[1]);
        v[0] = a.x; v[1] = a.y; v[2] = c.x; v[3] = c.y;
        float2 e = __half22float2(pHi[0]);
        float2 f = __half22float2(pHi[1]);
        z[0] = e.x; z[1] = e.y; z[2] = f.x; z[3] = f.y;
    }

    float sq = v[0]*v[0] + v[1]*v[1] + v[2]*v[2] + v[3]*v[3]
             + z[0]*z[0] + z[1]*z[1] + z[2]*z[2] + z[3]*z[3];
#pragma unroll
    for (int o = 16; o; o >>= 1) sq += __shfl_xor_sync(0xffffffffu, sq, o);
    const float rstd = rsqrtf(sq * (1.0f / 256.0f) + 1e-6f);

    const float p = (float)pos_ids[s];
    __half* dst = outp + ((size_t)(b * nh + head) * Sc + s) * HDc;
    float outLo[4], outHi[4];
#pragma unroll
    for (int i = 0; i < 4; i++) {
        float y = v[i] * rstd * (1.0f + w[d0 + i]);
        float zz = z[i] * rstd * (1.0f + w[128 + d0 + i]);
        float inv_freq = exp2f((float)(d0 + i) * (-13.2877123795494f / 128.0f));
        float sv, cv;
        __sincosf(p * inv_freq, &sv, &cv);
        outLo[i] = (y * cv - zz * sv) * oscale;
        outHi[i] = (zz * cv + y * sv) * oscale;
    }
    ((__half2*)(dst + d0))[0]       = __floats2half2_rn(outLo[0], outLo[1]);
    ((__half2*)(dst + d0))[1]       = __floats2half2_rn(outLo[2], outLo[3]);
    ((__half2*)(dst + 128 + d0))[0] = __floats2half2_rn(outHi[0], outHi[1]);
    ((__half2*)(dst + 128 + d0))[1] = __floats2half2_rn(outHi[2], outHi[3]);
}

// ===========================================================================
// FA2-style tensor-core flash attention (champion config).
// Warp w owns rows [q0+16w, q0+16w+16); tile-level causal skip; base-2 softmax.
// ===========================================================================
#define FQP 264
#define FVP 72
#define F_KS (128 * FQP)
#define F_VS (F_KS + 2 * 64 * FQP)
#define FLASH_SMEM ((F_VS + 2 * 256 * FVP) * 2)

__global__ __launch_bounds__(256, 1) void flash_attn_tc(
    const __half* __restrict__ qh, const __half* __restrict__ kh,
    const __half* __restrict__ vt, __half* __restrict__ ob)
{
    extern __shared__ __half sm[];
    __half* Qs  = sm;
    __half* Ks0 = sm + F_KS;
    __half* Vs0 = sm + F_VS;

    const int qt = gridDim.x - 1 - blockIdx.x;
    const int q0 = qt * 128;
    const int h = blockIdx.y, b = blockIdx.z;
    const int kvh = h >> 2;
    const int tid = threadIdx.x;
    const int w = tid >> 5, lane = tid & 31;
    const int lr = lane >> 2, lc = lane & 3;
    const int sel = lane >> 3, rr = lane & 7;

    const __half* Qg = qh + ((size_t)(b * Hc + h) * Sc + q0) * HDc;
    const __half* Kg = kh + ((size_t)(b * KVc + kvh) * Sc) * HDc;
    const __half* Vg = vt + ((size_t)(b * KVc + kvh) * HDc) * Sc;

    auto issue_kv = [&](int t, int buf) {
        const int j0 = t * 64;
        __half* Kd = Ks0 + buf * 64 * FQP;
        __half* Vd = Vs0 + buf * 256 * FVP;
#pragma unroll
        for (int i = 0; i < 8; i++) {
            int idx = tid + i * 256;
            int r = idx >> 5, ch = idx & 31;
            cpasync16(Kd + r * FQP + ch * 8, Kg + (size_t)(j0 + r) * HDc + ch * 8);
        }
#pragma unroll
        for (int i = 0; i < 8; i++) {
            int idx = tid + i * 256;
            int r = idx >> 3, ch = idx & 7;
            cpasync16(Vd + r * FVP + ch * 8, Vg + (size_t)r * Sc + j0 + ch * 8);
        }
    };

#pragma unroll
    for (int i = 0; i < 16; i++) {
        int idx = tid + i * 256;
        int r = idx >> 5, ch = idx & 31;
        cpasync16(Qs + r * FQP + ch * 8, Qg + (size_t)r * HDc + ch * 8);
    }
    issue_kv(0, 0);
    CP_COMMIT();

    const uint32_t smb = (uint32_t)__cvta_generic_to_shared(sm);
    const uint32_t qA   = smb + ((uint32_t)(w * 16 + (sel & 1) * 8 + rr) * FQP + (sel >> 1) * 8) * 2;
    const uint32_t kOff = ((uint32_t)((sel >> 1) * 8 + rr) * FQP + (sel & 1) * 8) * 2;
    const uint32_t vOff = ((uint32_t)((sel >> 1) * 8 + rr) * FVP + (sel & 1) * 8) * 2;

    float oacc[32][4];
#pragma unroll
    for (int i = 0; i < 32; i++)
#pragma unroll
        for (int j = 0; j < 4; j++) oacc[i][j] = 0.f;
    float m0v = -1e30f, m1v = -1e30f, l0 = 0.f, l1 = 0.f;

    const int qg0 = q0 + w * 16 + lr;
    const int qg1 = qg0 + 8;
    const int qmaxw = q0 + w * 16 + 15;
    const int ntiles = q0 / 64 + 2;

    for (int t = 0; t < ntiles; t++) {
        CP_WAIT0();
        __syncthreads();
        if (t + 1 < ntiles) { issue_kv(t + 1, (t + 1) & 1); CP_COMMIT(); }
        const int j0 = t * 64;

        if (j0 <= qmaxw) {
            const uint32_t kB = smb + (uint32_t)(F_KS + (t & 1) * 64 * FQP) * 2 + kOff;
            const uint32_t vB = smb + (uint32_t)(F_VS + (t & 1) * 256 * FVP) * 2 + vOff;

            float sacc[8][4];
#pragma unroll
            for (int i = 0; i < 8; i++)
#pragma unroll
                for (int j = 0; j < 4; j++) sacc[i][j] = 0.f;
#pragma unroll
            for (int kc = 0; kc < 16; kc++) {
                uint32_t a[4];
                ldsm_x4(a, qA + kc * 32);
#pragma unroll
                for (int tp = 0; tp < 4; tp++) {
                    uint32_t bb[4];
                    ldsm_x4(bb, kB + (uint32_t)(tp * 16 * FQP) * 2 + kc * 32);
                    MMA_F16(sacc[2 * tp], a, (&bb[0]));
                    MMA_F16(sacc[2 * tp + 1], a, (&bb[2]));
                }
            }

            if (j0 + 63 > q0 + w * 16) {
#pragma unroll
                for (int nf = 0; nf < 8; nf++) {
                    int j = j0 + 8 * nf + 2 * lc;
                    if (j > qg0)     sacc[nf][0] = -1e30f;
                    if (j + 1 > qg0) sacc[nf][1] = -1e30f;
                    if (j > qg1)     sacc[nf][2] = -1e30f;
                    if (j + 1 > qg1) sacc[nf][3] = -1e30f;
                }
            }

            float mx0 = -1e30f, mx1 = -1e30f;
#pragma unroll
            for (int nf = 0; nf < 8; nf++) {
                mx0 = fmaxf(mx0, fmaxf(sacc[nf][0], sacc[nf][1]));
                mx1 = fmaxf(mx1, fmaxf(sacc[nf][2], sacc[nf][3]));
            }
            mx0 = fmaxf(mx0, __shfl_xor_sync(0xffffffffu, mx0, 1));
            mx0 = fmaxf(mx0, __shfl_xor_sync(0xffffffffu, mx0, 2));
            mx1 = fmaxf(mx1, __shfl_xor_sync(0xffffffffu, mx1, 1));
            mx1 = fmaxf(mx1, __shfl_xor_sync(0xffffffffu, mx1, 2));
            float mn0 = fmaxf(m0v, mx0), mn1 = fmaxf(m1v, mx1);
            float alpha0 = ex2(m0v - mn0);
            float alpha1 = ex2(m1v - mn1);
            m0v = mn0; m1v = mn1;

            float ps0 = 0.f, ps1 = 0.f;
#pragma unroll
            for (int nf = 0; nf < 8; nf++) {
                sacc[nf][0] = ex2(sacc[nf][0] - mn0);
                sacc[nf][1] = ex2(sacc[nf][1] - mn0);
                sacc[nf][2] = ex2(sacc[nf][2] - mn1);
                sacc[nf][3] = ex2(sacc[nf][3] - mn1);
                ps0 += sacc[nf][0] + sacc[nf][1];
                ps1 += sacc[nf][2] + sacc[nf][3];
            }
            ps0 += __shfl_xor_sync(0xffffffffu, ps0, 1);
            ps0 += __shfl_xor_sync(0xffffffffu, ps0, 2);
            ps1 += __shfl_xor_sync(0xffffffffu, ps1, 1);
            ps1 += __shfl_xor_sync(0xffffffffu, ps1, 2);
            l0 = l0 * alpha0 + ps0;
            l1 = l1 * alpha1 + ps1;

#pragma unroll
            for (int nf = 0; nf < 32; nf++) {
                oacc[nf][0] *= alpha0; oacc[nf][1] *= alpha0;
                oacc[nf][2] *= alpha1; oacc[nf][3] *= alpha1;
            }

#pragma unroll
            for (int kc = 0; kc < 4; kc++) {
                uint32_t pa[4];
                pa[0] = packh2(sacc[2 * kc][0],     sacc[2 * kc][1]);
                pa[1] = packh2(sacc[2 * kc][2],     sacc[2 * kc][3]);
                pa[2] = packh2(sacc[2 * kc + 1][0], sacc[2 * kc + 1][1]);
                pa[3] = packh2(sacc[2 * kc + 1][2], sacc[2 * kc + 1][3]);
#pragma unroll
                for (int tp = 0; tp < 16; tp++) {
                    uint32_t bb[4];
                    ldsm_x4(bb, vB + (uint32_t)(tp * 16 * FVP) * 2 + kc * 32);
                    MMA_F16(oacc[2 * tp], pa, (&bb[0]));
                    MMA_F16(oacc[2 * tp + 1], pa, (&bb[2]));
                }
            }
        }
    }

    const float inv0 = 1.f / l0;
    const float inv1 = 1.f / l1;
#pragma unroll
    for (int nf = 0; nf < 32; nf++) {
        int col = h * HDc + 8 * nf + 2 * lc;
        size_t r0a = (size_t)(b * Sc + q0 + w * 16 + lr) * (Hc * HDc) + col;
        size_t r1a = (size_t)(b * Sc + q0 + w * 16 + lr + 8) * (Hc * HDc) + col;
        *(__half2*)(ob + r0a) = __floats2half2_rn(oacc[nf][0] * inv0, oacc[nf][1] * inv0);
        *(__half2*)(ob + r1a) = __floats2half2_rn(oacc[nf][2] * inv1, oacc[nf][3] * inv1);
    }
}

// ---------------------------------------------------------------------------
extern "C" void kernel_launch(void* const* d_in, const int* in_sizes, int n_in,
                              void* d_out, int out_size)
{
    const float* hidden = (const float*)d_in[0];
    const float* Wq = (const float*)d_in[1];
    const float* Wk = (const float*)d_in[2];
    const float* Wv = (const float*)d_in[3];
    const float* Wo = (const float*)d_in[4];
    const float* qw = (const float*)d_in[5];
    const float* kw = (const float*)d_in[6];
    const int*  pos = (const int*)d_in[7];
    float* out = (float*)d_out;

    __half *qkvh, *qhh, *khh, *vth, *ah, *hh, *wqkvT, *woT;
    cudaGetSymbolAddress((void**)&qkvh, g_qkvh);
    cudaGetSymbolAddress((void**)&qhh, g_qh);
    cudaGetSymbolAddress((void**)&khh, g_kh);
    cudaGetSymbolAddress((void**)&vth, g_vt);
    cudaGetSymbolAddress((void**)&ah, g_attn_h);
    cudaGetSymbolAddress((void**)&hh, g_hh);
    cudaGetSymbolAddress((void**)&wqkvT, g_wqkvT);
    cudaGetSymbolAddress((void**)&woT, g_woT);

    const int M = Bc * Sc;           // 4096
    const int NQ = Hc * HDc;         // 4096
    const int NKV = KVc * HDc;       // 1024

    cudaFuncSetAttribute(gemm_f16<__half>, cudaFuncAttributeMaxDynamicSharedMemorySize, GEMM_SMEM);
    cudaFuncSetAttribute(gemm_f16<float>, cudaFuncAttributeMaxDynamicSharedMemorySize, GEMM_SMEM);
    cudaFuncSetAttribute(flash_attn_tc, cudaFuncAttributeMaxDynamicSharedMemorySize, FLASH_SMEM);

    // Side streams + events for capturable fork/join
    cudaStream_t s1, s2;
    cudaStreamCreateWithFlags(&s1, cudaStreamNonBlocking);
    cudaStreamCreateWithFlags(&s2, cudaStreamNonBlocking);
    cudaEvent_t evRoot, evKV, evQ, evWo, evG, evVt;
    cudaEventCreateWithFlags(&evRoot, cudaEventDisableTiming);
    cudaEventCreateWithFlags(&evKV, cudaEventDisableTiming);
    cudaEventCreateWithFlags(&evQ, cudaEventDisableTiming);
    cudaEventCreateWithFlags(&evWo, cudaEventDisableTiming);
    cudaEventCreateWithFlags(&evG, cudaEventDisableTiming);
    cudaEventCreateWithFlags(&evVt, cudaEventDisableTiming);

    cudaEventRecord(evRoot, 0);
    cudaStreamWaitEvent(s1, evRoot, 0);
    cudaStreamWaitEvent(s2, evRoot, 0);

    // main: hidden -> fp16
    {
        int n4 = M * Dc / 4;
        to_half<<<(n4 + 255) / 256, 256>>>((const float4*)hidden, hh, n4);
    }
    // s1: Wk, Wv, then Wo
    transpose_half<<<dim3(NKV / 32, Dc / 32), 256, 0, s1>>>(Wk, wqkvT + (size_t)NQ * Dc, Dc, NKV);
    transpose_half<<<dim3(NKV / 32, Dc / 32), 256, 0, s1>>>(Wv, wqkvT + (size_t)(NQ + NKV) * Dc, Dc, NKV);
    cudaEventRecord(evKV, s1);
    transpose_half<<<dim3(Dc / 32, NQ / 32), 256, 0, s1>>>(Wo, woT, NQ, Dc);
    cudaEventRecord(evWo, s1);
    // s2: Wq
    transpose_half<<<dim3(NQ / 32, Dc / 32), 256, 0, s2>>>(Wq, wqkvT, Dc, NQ);
    cudaEventRecord(evQ, s2);

    // join -> fused QKV projection
    cudaStreamWaitEvent(0, evKV, 0);
    cudaStreamWaitEvent(0, evQ, 0);
    gemm_f16<__half><<<dim3(NQKV / BN, M / BM), 256, GEMM_SMEM>>>(hh, wqkvT, qkvh, M, NQKV, Dc);

    // fork: transpose_vt (s1) parallel with rmsnorm (main)
    cudaEventRecord(evG, 0);
    cudaStreamWaitEvent(s1, evG, 0);
    transpose_vt<<<dim3(HDc / 32, Sc / 32, Bc * KVc), 256, 0, s1>>>(qkvh + NQ + NKV, vth);
    cudaEventRecord(evVt, s1);
    rmsnorm_rope_qk<<<M * (Hc + KVc) / 8, 256>>>(qkvh, qhh, khh, qw, kw, pos);

    // join: flash (single full-range launch; heavy tiles first)
    cudaStreamWaitEvent(0, evVt, 0);
    flash_attn_tc<<<dim3(Sc / 128, Hc, Bc), 256, FLASH_SMEM>>>(qhh, khh, vth, ah);

    // join Wo, output projection
    cudaStreamWaitEvent(0, evWo, 0);
    gemm_f16<float><<<dim3(Dc / BN, M / BM), 256, GEMM_SMEM>>>(ah, woT, out, M, Dc, NQ);

    cudaEventDestroy(evRoot);
    cudaEventDestroy(evKV);
    cudaEventDestroy(evQ);
    cudaEventDestroy(evWo);
    cudaEventDestroy(evG);
    cudaEventDestroy(evVt);
    cudaStreamDestroy(s1);
    cudaStreamDestroy(s2);
}